// round 1
// baseline (speedup 1.0000x reference)
#include <cuda_runtime.h>

// VectorQuantizer: B=32, C=64, H=64, W=64, K=512
// Inputs:  d_in[0]=x [B,C,H,W] f32, d_in[1]=codebook [K,C] f32,
//          d_in[2]=ema_cluster_size [K] f32, d_in[3]=ema_weight [K,C] f32
// Output (flattened tuple, all f32):
//   [0, 8388608)          out = x + (quantized - x)   (layout [B,C,H,W])
//   [8388608]             commitment_loss
//   [8388609]             unique_codes
//   [8388610, +32768)     new_codebook [K,C]

#define B_  32
#define C_  64
#define HW_ 4096
#define N_  131072      // B*H*W
#define K_  512
#define OUT_ELEMS 8388608

typedef unsigned long long u64;

// persistent scratch (no allocations allowed) — zeroed every launch
__device__ float g_counts[K_];
__device__ float g_sums[K_ * C_];
__device__ float g_commit;

// ---- packed fp32x2 helpers (sm_103a doubles fp32 rate via f32x2) ----
__device__ __forceinline__ u64 fma2(u64 a, u64 b, u64 c) {
    u64 d;
    asm("fma.rn.f32x2 %0, %1, %2, %3;" : "=l"(d) : "l"(a), "l"(b), "l"(c));
    return d;
}
__device__ __forceinline__ u64 add2(u64 a, u64 b) {
    u64 d;
    asm("add.rn.f32x2 %0, %1, %2;" : "=l"(d) : "l"(a), "l"(b));
    return d;
}
__device__ __forceinline__ u64 pack2(float lo, float hi) {
    u64 d;
    asm("mov.b64 %0, {%1, %2};" : "=l"(d) : "f"(lo), "f"(hi));
    return d;
}
__device__ __forceinline__ void unpack2(u64 d, float& lo, float& hi) {
    asm("mov.b64 {%0, %1}, %2;" : "=f"(lo), "=f"(hi) : "l"(d));
}

// ---------------- zero scratch ----------------
__global__ void __launch_bounds__(512, 1) vq_zero() {
    int i = blockIdx.x * blockDim.x + threadIdx.x;
    if (i < K_ * C_) g_sums[i] = 0.f;
    if (i < K_) g_counts[i] = 0.f;
    if (i == 0) g_commit = 0.f;
}

// ---------------- per-row epilogue ----------------
__device__ __forceinline__ void epilogue_row(
    int n, const u64* xr, int bestk,
    float* __restrict__ out, const float* __restrict__ cb,
    float* s_counts, float& csum)
{
    int b = n >> 12, hw = n & 4095;
    float* op = out + (size_t)b * C_ * HW_ + hw;
    const float4* qp = (const float4*)(cb + bestk * C_);   // L2-hot global read
    atomicAdd(&s_counts[bestk], 1.0f);
    float* sp = &g_sums[bestk * C_];
#pragma unroll
    for (int j = 0; j < 16; j++) {
        float4 q = qp[j];
        float x0, x1, x2, x3;
        unpack2(xr[2 * j],     x0, x1);
        unpack2(xr[2 * j + 1], x2, x3);
        // out = x + (q - x): match reference fp expression exactly
        op[(4 * j + 0) * HW_] = x0 + (q.x - x0);
        op[(4 * j + 1) * HW_] = x1 + (q.y - x1);
        op[(4 * j + 2) * HW_] = x2 + (q.z - x2);
        op[(4 * j + 3) * HW_] = x3 + (q.w - x3);
        float d0 = x0 - q.x, d1 = x1 - q.y, d2 = x2 - q.z, d3 = x3 - q.w;
        csum += d0 * d0 + d1 * d1 + d2 * d2 + d3 * d3;
        // vectorized no-return reduction into segment sums
        asm volatile("red.global.add.v4.f32 [%0], {%1,%2,%3,%4};"
                     :: "l"(sp + 4 * j), "f"(x0), "f"(x1), "f"(x2), "f"(x3)
                     : "memory");
    }
}

// ---------------- main fused kernel ----------------
// grid = 256 blocks x 256 threads, 2 rows per thread -> exactly N_ rows
__global__ void __launch_bounds__(256, 1) vq_main(
    const float* __restrict__ x, const float* __restrict__ cb,
    float* __restrict__ out)
{
    extern __shared__ float smem[];            // [0,32768): codebook
    float* s_esq    = smem + K_ * C_;          // 512
    float* s_counts = s_esq + K_;              // 512
    float* s_red    = s_counts + K_;           // 32 (8 used)
    int tid = threadIdx.x;

    // load codebook (128KB) into SMEM, coalesced float4
    float4* sc4 = (float4*)smem;
    const float4* cg = (const float4*)cb;
#pragma unroll
    for (int i = 0; i < 32; i++) sc4[tid + i * 256] = cg[tid + i * 256];

    // per-code |e|^2 (from L2-cached global) + zero shared histogram
#pragma unroll
    for (int r = 0; r < 2; r++) {
        int k = tid + r * 256;
        const float4* row = cg + k * 16;
        float s = 0.f;
#pragma unroll
        for (int j = 0; j < 16; j++) {
            float4 v = row[j];
            s += v.x * v.x + v.y * v.y + v.z * v.z + v.w * v.w;
        }
        s_esq[k] = s;
        s_counts[k] = 0.f;
    }
    __syncthreads();

    int n0 = blockIdx.x * 512 + tid;   // rows [blk*512, blk*512+255]
    int n1 = n0 + 256;                 // rows [blk*512+256, blk*512+511]

    // load both x rows (channel stride HW_, coalesced across threads), pack f32x2
    u64 xa[32], xb[32];
    {
        const float* xp = x + (size_t)(n0 >> 12) * C_ * HW_ + (n0 & 4095);
        const float* yp = x + (size_t)(n1 >> 12) * C_ * HW_ + (n1 & 4095);
#pragma unroll
        for (int i = 0; i < 32; i++) {
            xa[i] = pack2(xp[(2 * i) * HW_], xp[(2 * i + 1) * HW_]);
            xb[i] = pack2(yp[(2 * i) * HW_], yp[(2 * i + 1) * HW_]);
        }
    }

    // argmin over K codes: dist = |e|^2 - 2 x.e  (|x|^2 constant per row)
    float bestA = 3.402823466e38f, bestB = 3.402823466e38f;
    int kA = 0, kB = 0;
    const ulonglong2* cbase = (const ulonglong2*)smem;
    for (int k = 0; k < K_; k++) {
        const ulonglong2* cp = cbase + (k << 4);   // 16B-granular, SW-free broadcast
        u64 a0 = 0, a1 = 0, a2 = 0, a3 = 0;
        u64 b0 = 0, b1 = 0, b2 = 0, b3 = 0;
#pragma unroll
        for (int j = 0; j < 16; j += 2) {
            ulonglong2 p = cp[j];
            ulonglong2 q = cp[j + 1];
            a0 = fma2(xa[2 * j],     p.x, a0);
            a1 = fma2(xa[2 * j + 1], p.y, a1);
            b0 = fma2(xb[2 * j],     p.x, b0);
            b1 = fma2(xb[2 * j + 1], p.y, b1);
            a2 = fma2(xa[2 * j + 2], q.x, a2);
            a3 = fma2(xa[2 * j + 3], q.y, a3);
            b2 = fma2(xb[2 * j + 2], q.x, b2);
            b3 = fma2(xb[2 * j + 3], q.y, b3);
        }
        a0 = add2(a0, a1); a2 = add2(a2, a3); a0 = add2(a0, a2);
        b0 = add2(b0, b1); b2 = add2(b2, b3); b0 = add2(b0, b2);
        float alo, ahi, blo, bhi;
        unpack2(a0, alo, ahi);
        unpack2(b0, blo, bhi);
        float esq = s_esq[k];
        float dA = fmaf(-2.f, alo + ahi, esq);
        float dB = fmaf(-2.f, blo + bhi, esq);
        if (dA < bestA) { bestA = dA; kA = k; }   // strict <: first index wins
        if (dB < bestB) { bestB = dB; kB = k; }
    }

    float csum = 0.f;
    epilogue_row(n0, xa, kA, out, cb, s_counts, csum);
    epilogue_row(n1, xb, kB, out, cb, s_counts, csum);

    // block-reduce commitment partial -> one global atomic per block
#pragma unroll
    for (int off = 16; off > 0; off >>= 1)
        csum += __shfl_down_sync(0xffffffffu, csum, off);
    int warp = tid >> 5, lane = tid & 31;
    if (lane == 0) s_red[warp] = csum;
    __syncthreads();
    if (warp == 0) {
        float v = (lane < 8) ? s_red[lane] : 0.f;
#pragma unroll
        for (int off = 4; off > 0; off >>= 1)
            v += __shfl_down_sync(0xffffffffu, v, off);
        if (lane == 0) atomicAdd(&g_commit, v);
    }

    // flush shared histogram -> global counts (exact integer arithmetic in f32)
#pragma unroll
    for (int r = 0; r < 2; r++) {
        int k = tid + r * 256;
        float c = s_counts[k];
        if (c != 0.f) atomicAdd(&g_counts[k], c);
    }
}

// ---------------- finalize: EMA update, scalars ----------------
__global__ void __launch_bounds__(512, 1) vq_finalize(
    const float* __restrict__ ema_cs, const float* __restrict__ ema_w,
    float* __restrict__ out)
{
    __shared__ float s_n[K_];
    __shared__ float s_u[K_];
    int k = threadIdx.x;
    float cnt = g_counts[k];
    float ncs = 0.99f * ema_cs[k] + 0.01f * cnt;
    s_n[k] = ncs;
    s_u[k] = (cnt > 0.f) ? 1.f : 0.f;
    __syncthreads();
#pragma unroll
    for (int off = 256; off > 0; off >>= 1) {
        if (k < off) { s_n[k] += s_n[k + off]; s_u[k] += s_u[k + off]; }
        __syncthreads();
    }
    float n = s_n[0];
    float smoothed = (ncs + 1e-5f) / (n + K_ * 1e-5f) * n;
    float* cbo = out + OUT_ELEMS + 2;
#pragma unroll 4
    for (int c = 0; c < C_; c++) {
        int i = k * C_ + c;
        cbo[i] = (0.99f * ema_w[i] + 0.01f * g_sums[i]) / smoothed;
    }
    if (k == 0) {
        out[OUT_ELEMS]     = g_commit * (1.0f / 8388608.0f);  // mean, exact 2^-23
        out[OUT_ELEMS + 1] = s_u[0];
    }
}

// ---------------- launch ----------------
extern "C" void kernel_launch(void* const* d_in, const int* in_sizes, int n_in,
                              void* d_out, int out_size) {
    const float* x   = (const float*)d_in[0];
    const float* cb  = (const float*)d_in[1];
    const float* ecs = (const float*)d_in[2];
    const float* ew  = (const float*)d_in[3];
    float* out = (float*)d_out;

    const int SMEM = (K_ * C_ + K_ + K_ + 32) * (int)sizeof(float);  // 135296 B
    cudaFuncSetAttribute(vq_main, cudaFuncAttributeMaxDynamicSharedMemorySize, SMEM);

    vq_zero<<<65, 512>>>();
    vq_main<<<256, 256, SMEM>>>(x, cb, out);
    vq_finalize<<<1, 512>>>(ecs, ew, out);
}